// round 14
// baseline (speedup 1.0000x reference)
#include <cuda_runtime.h>
#include <cuda_fp16.h>
#include <cuda_bf16.h>

#define NN 50000
#define DD 128
#define CAP 96           // bucket capacity per node; P(Poisson(32) >= 96) ~ 1e-18

typedef unsigned int uint;

// Scratch (no allocation allowed). g_edges is zero-initialized at module load;
// slots beyond each node's degree are NEVER written, so they stay
// (src=0, w=half2(0,0)) forever -> safe zero-weight padding for the rounded-up
// gather waves (row 0 is L1-hot; padding still costs L1 wavefronts, hence the
// smaller static tail wave).
__device__ __half g_sup[(size_t)NN * DD];   // support (gather operand), fp16
__device__ __half g_h[(size_t)NN * DD];     // hidden layer, fp16
__device__ __half g_w1t[DD * DD];           // W1^T fp16 ([n][k])
__device__ __half g_w2t[DD * DD];           // W2^T fp16
__device__ int    g_cursor[NN];             // per-node fill cursor == degree
__device__ int2   g_edges[(size_t)NN * CAP]; // (src, weight-as-half2-broadcast)

// ---------------------------------------------------------------------------
// Prep: zero cursors + convert/transpose both weight matrices to fp16.
// ---------------------------------------------------------------------------
__global__ void prep_kernel(const float* __restrict__ W1, const float* __restrict__ W2,
                            __half* __restrict__ W1t, __half* __restrict__ W2t,
                            int* __restrict__ cursor)
{
    int idx = blockIdx.x * blockDim.x + threadIdx.x;
    if (idx < NN) cursor[idx] = 0;
    if (idx < DD * DD) {
        int k = idx >> 7;
        int n = idx & 127;
        W1t[n * DD + k] = __float2half(W1[idx]);
        W2t[n * DD + k] = __float2half(W2[idx]);
    }
}

// ---------------------------------------------------------------------------
// HGEMM via mma.sync m16n8k16 (fp16 in, fp32 acc, fp16 out). R10 verbatim.
// ---------------------------------------------------------------------------
#define GEMM_SMEM ((64 + 128) * 136 * 2)

template <typename InT, bool RELU>
__global__ __launch_bounds__(256) void hgemm_kernel(
    const InT* __restrict__ X, const __half* __restrict__ Wt,
    __half* __restrict__ out)
{
    extern __shared__ __align__(16) __half sh[];
    __half (*Ash)[136] = reinterpret_cast<__half(*)[136]>(sh);            // 64 x 136
    __half (*Bsh)[136] = reinterpret_cast<__half(*)[136]>(sh + 64 * 136); // 128 x 136

    const int tid = threadIdx.x;
    const int lane = tid & 31;
    const int wid = tid >> 5;
    const int block_row = blockIdx.x * 64;

#pragma unroll
    for (int i = 0; i < 16; i++) {
        int idx = tid + i * 256;
        int n = idx >> 5;
        int c4 = (idx & 31) * 4;
        uint2 v = *(const uint2*)(Wt + n * DD + c4);
        *(uint2*)&Bsh[n][c4] = v;
    }

    if constexpr (sizeof(InT) == 4) {
#pragma unroll
        for (int i = 0; i < 8; i++) {
            int idx = tid + i * 256;
            int r = idx >> 5;
            int c4 = (idx & 31) * 4;
            int gr = block_row + r;
            float4 v = make_float4(0.f, 0.f, 0.f, 0.f);
            if (gr < NN) v = *(const float4*)((const float*)X + (size_t)gr * DD + c4);
            if (RELU) {
                v.x = fmaxf(v.x, 0.f); v.y = fmaxf(v.y, 0.f);
                v.z = fmaxf(v.z, 0.f); v.w = fmaxf(v.w, 0.f);
            }
            __half2 h0 = __floats2half2_rn(v.x, v.y);
            __half2 h1 = __floats2half2_rn(v.z, v.w);
            uint2 pk;
            pk.x = *reinterpret_cast<uint*>(&h0);
            pk.y = *reinterpret_cast<uint*>(&h1);
            *(uint2*)&Ash[r][c4] = pk;
        }
    } else {
#pragma unroll
        for (int i = 0; i < 8; i++) {
            int idx = tid + i * 256;
            int r = idx >> 5;
            int c4 = (idx & 31) * 4;
            int gr = block_row + r;
            uint2 v = make_uint2(0u, 0u);
            if (gr < NN) v = *(const uint2*)((const __half*)X + (size_t)gr * DD + c4);
            if (RELU) {
                __half2 z = __float2half2_rn(0.f);
                __half2 a = __hmax2(*reinterpret_cast<__half2*>(&v.x), z);
                __half2 b = __hmax2(*reinterpret_cast<__half2*>(&v.y), z);
                v.x = *reinterpret_cast<uint*>(&a);
                v.y = *reinterpret_cast<uint*>(&b);
            }
            *(uint2*)&Ash[r][c4] = v;
        }
    }
    __syncthreads();

    const int warp_m = (wid >> 2) * 32;
    const int warp_n = (wid & 3) * 32;
    const int gr = lane >> 2;
    const int qc = lane & 3;

    float acc[2][4][4];
#pragma unroll
    for (int mt = 0; mt < 2; mt++)
#pragma unroll
        for (int nt = 0; nt < 4; nt++)
#pragma unroll
            for (int j = 0; j < 4; j++) acc[mt][nt][j] = 0.f;

#pragma unroll
    for (int k0 = 0; k0 < DD; k0 += 16) {
        int kc = k0 + 2 * qc;
        uint a[2][4];
#pragma unroll
        for (int mt = 0; mt < 2; mt++) {
            int r0 = warp_m + mt * 16 + gr;
            a[mt][0] = *(const uint*)&Ash[r0][kc];
            a[mt][1] = *(const uint*)&Ash[r0 + 8][kc];
            a[mt][2] = *(const uint*)&Ash[r0][kc + 8];
            a[mt][3] = *(const uint*)&Ash[r0 + 8][kc + 8];
        }
#pragma unroll
        for (int nt = 0; nt < 4; nt++) {
            int n = warp_n + nt * 8 + gr;
            uint b0 = *(const uint*)&Bsh[n][kc];
            uint b1 = *(const uint*)&Bsh[n][kc + 8];
#pragma unroll
            for (int mt = 0; mt < 2; mt++) {
                asm volatile(
                    "mma.sync.aligned.m16n8k16.row.col.f32.f16.f16.f32 "
                    "{%0,%1,%2,%3}, {%4,%5,%6,%7}, {%8,%9}, {%0,%1,%2,%3};"
                    : "+f"(acc[mt][nt][0]), "+f"(acc[mt][nt][1]),
                      "+f"(acc[mt][nt][2]), "+f"(acc[mt][nt][3])
                    : "r"(a[mt][0]), "r"(a[mt][1]), "r"(a[mt][2]), "r"(a[mt][3]),
                      "r"(b0), "r"(b1));
            }
        }
    }

#pragma unroll
    for (int mt = 0; mt < 2; mt++) {
        int r0 = block_row + warp_m + mt * 16 + gr;
#pragma unroll
        for (int nt = 0; nt < 4; nt++) {
            int col = warp_n + nt * 8 + 2 * qc;
            if (r0 < NN) {
                __half2 p = __floats2half2_rn(acc[mt][nt][0], acc[mt][nt][1]);
                *(__half2*)(out + (size_t)r0 * DD + col) = p;
            }
            if (r0 + 8 < NN) {
                __half2 p = __floats2half2_rn(acc[mt][nt][2], acc[mt][nt][3]);
                *(__half2*)(out + (size_t)(r0 + 8) * DD + col) = p;
            }
        }
    }
}

// ---------------------------------------------------------------------------
// Bucket fill: one edge per thread. Weight pre-converted to broadcast half2.
// ---------------------------------------------------------------------------
__global__ void fill_kernel(
    const int* __restrict__ src, const int* __restrict__ dst,
    const float* __restrict__ w, int* __restrict__ cursor,
    int2* __restrict__ edges, int nE)
{
    int e = blockIdx.x * blockDim.x + threadIdx.x;
    if (e >= nE) return;
    int d = __ldg(dst + e);
    int slot = atomicAdd(cursor + d, 1);
    __half2 w2 = __float2half2_rn(__ldg(w + e));
    edges[(size_t)d * CAP + slot] =
        make_int2(__ldg(src + e), (int)*reinterpret_cast<uint*>(&w2));
}

// ---------------------------------------------------------------------------
// Gather: warp per node, 16 lanes per edge. Statically unrolled wave body
// (EHALF = edges per half-warp: 8 for 16-edge waves, 4 for the 8-edge tail).
// HFMA2 per-wave accumulation, fp32 flush. Padding slots are (0,0).
// ---------------------------------------------------------------------------
template <int EHALF>
__device__ __forceinline__ void gather_wave(
    const __half* __restrict__ sup, const int2* __restrict__ ebase,
    int k, int row_off, float* acc)
{
    __half2 w2[EHALF];
    const __half* rp[EHALF];
#pragma unroll
    for (int u = 0; u < EHALF; u++) {
        int2 p = __ldg(ebase + k + 2 * u);
        w2[u] = *reinterpret_cast<__half2*>(&p.y);
        rp[u] = sup + (size_t)p.x * DD + row_off;
    }
    uint4 v[EHALF];
#pragma unroll
    for (int u = 0; u < EHALF; u++) v[u] = *(const uint4*)rp[u];

    __half2 hacc[4];
#pragma unroll
    for (int j = 0; j < 4; j++) hacc[j] = __float2half2_rn(0.f);
#pragma unroll
    for (int u = 0; u < EHALF; u++) {
        hacc[0] = __hfma2(w2[u], *reinterpret_cast<__half2*>(&v[u].x), hacc[0]);
        hacc[1] = __hfma2(w2[u], *reinterpret_cast<__half2*>(&v[u].y), hacc[1]);
        hacc[2] = __hfma2(w2[u], *reinterpret_cast<__half2*>(&v[u].z), hacc[2]);
        hacc[3] = __hfma2(w2[u], *reinterpret_cast<__half2*>(&v[u].w), hacc[3]);
    }
#pragma unroll
    for (int j = 0; j < 4; j++) {
        float2 f = __half22float2(hacc[j]);
        acc[2 * j + 0] += f.x;
        acc[2 * j + 1] += f.y;
    }
}

template <typename OutT>
__global__ __launch_bounds__(256) void gather_kernel(
    const __half* __restrict__ sup,
    const int2* __restrict__ edges,
    const int* __restrict__ cursor, const float* __restrict__ bias,
    OutT* __restrict__ out)
{
    int n = (int)((blockIdx.x * (unsigned)blockDim.x + threadIdx.x) >> 5);
    int lane = threadIdx.x & 31;
    if (n >= NN) return;

    const int half_id = lane >> 4;
    const int fl = lane & 15;

    const int2* ebase = edges + (size_t)n * CAP + half_id;
    const int row_off = fl * 8;
    int deg = __ldg(cursor + n);

    float acc[8];
#pragma unroll
    for (int j = 0; j < 8; j++) acc[j] = 0.f;

    int k = 0;
    for (; k + 16 <= deg; k += 16)
        gather_wave<8>(sup, ebase, k, row_off, acc);
    int rem = deg - k;                        // 0..15
    if (rem > 8)       gather_wave<8>(sup, ebase, k, row_off, acc);  // padded 16
    else if (rem > 0)  gather_wave<4>(sup, ebase, k, row_off, acc);  // padded 8

#pragma unroll
    for (int j = 0; j < 8; j++)
        acc[j] += __shfl_xor_sync(0xffffffffu, acc[j], 16);

    if (lane < 16) {
        const float* bp = bias + row_off;
#pragma unroll
        for (int j = 0; j < 8; j++) acc[j] += __ldg(bp + j);

        if constexpr (sizeof(OutT) == 4) {
            float* op = (float*)out + (size_t)n * DD + row_off;
            *(float4*)(op) = make_float4(acc[0], acc[1], acc[2], acc[3]);
            *(float4*)(op + 4) = make_float4(acc[4], acc[5], acc[6], acc[7]);
        } else {
            __half2 h0 = __floats2half2_rn(acc[0], acc[1]);
            __half2 h1 = __floats2half2_rn(acc[2], acc[3]);
            __half2 h2 = __floats2half2_rn(acc[4], acc[5]);
            __half2 h3 = __floats2half2_rn(acc[6], acc[7]);
            uint4 pk;
            pk.x = *reinterpret_cast<uint*>(&h0);
            pk.y = *reinterpret_cast<uint*>(&h1);
            pk.z = *reinterpret_cast<uint*>(&h2);
            pk.w = *reinterpret_cast<uint*>(&h3);
            *(uint4*)((__half*)out + (size_t)n * DD + row_off) = pk;
        }
    }
}

// ---------------------------------------------------------------------------
// kernel_launch — plain serial pipeline (R10 structure; overlap abandoned).
// ---------------------------------------------------------------------------
extern "C" void kernel_launch(void* const* d_in, const int* in_sizes, int n_in,
                              void* d_out, int out_size)
{
    const float* features = (const float*)d_in[0];
    const int*   edge_src = (const int*)d_in[1];
    const int*   edge_dst = (const int*)d_in[2];
    const float* edge_w   = (const float*)d_in[3];
    const float* W1       = (const float*)d_in[4];
    const float* b1       = (const float*)d_in[5];
    const float* W2       = (const float*)d_in[6];
    const float* b2       = (const float*)d_in[7];
    float* out = (float*)d_out;

    const int nE = in_sizes[1];

    __half* sup;  cudaGetSymbolAddress((void**)&sup, g_sup);
    __half* h;    cudaGetSymbolAddress((void**)&h, g_h);
    __half* w1t;  cudaGetSymbolAddress((void**)&w1t, g_w1t);
    __half* w2t;  cudaGetSymbolAddress((void**)&w2t, g_w2t);
    int* cursor;  cudaGetSymbolAddress((void**)&cursor, g_cursor);
    int2* edges;  cudaGetSymbolAddress((void**)&edges, g_edges);

    cudaFuncSetAttribute(hgemm_kernel<float, false>,
                         cudaFuncAttributeMaxDynamicSharedMemorySize, GEMM_SMEM);
    cudaFuncSetAttribute(hgemm_kernel<__half, true>,
                         cudaFuncAttributeMaxDynamicSharedMemorySize, GEMM_SMEM);

    const int gemm_grid = (NN + 63) / 64;
    const int edge_grid = (nE + 255) / 256;
    const int prep_grid = (NN + 255) / 256;
    const int gather_grid = (NN * 32 + 255) / 256;

    prep_kernel<<<prep_grid, 256>>>(W1, W2, w1t, w2t, cursor);
    fill_kernel<<<edge_grid, 256>>>(edge_src, edge_dst, edge_w, cursor, edges, nE);

    hgemm_kernel<float, false><<<gemm_grid, 256, GEMM_SMEM>>>(features, w1t, sup);
    gather_kernel<__half><<<gather_grid, 256>>>(sup, edges, cursor, b1, h);

    hgemm_kernel<__half, true><<<gemm_grid, 256, GEMM_SMEM>>>(h, w2t, sup);
    gather_kernel<float><<<gather_grid, 256>>>(sup, edges, cursor, b2, out);
}

// round 16
// speedup vs baseline: 1.0875x; 1.0875x over previous
#include <cuda_runtime.h>
#include <cuda_fp16.h>
#include <cuda_bf16.h>

#define NN 50000
#define DD 128
#define CAP 96           // bucket capacity per node; P(Poisson(32) >= 96) ~ 1e-18

typedef unsigned int uint;

// Scratch (no allocation allowed). g_edges is zero-initialized at module load;
// slots beyond each node's degree are NEVER written, so they stay
// (src=0, w=half2(0,0)) forever -> safe zero-weight padding for the rounded-up
// gather loop (row 0 is L1-hot).
__device__ __half g_sup[(size_t)NN * DD];   // support (gather operand), fp16
__device__ __half g_h[(size_t)NN * DD];     // hidden layer, fp16
__device__ __half g_w1t[DD * DD];           // W1^T fp16 ([n][k])
__device__ __half g_w2t[DD * DD];           // W2^T fp16
__device__ int    g_cursor[NN];             // per-node fill cursor == degree
__device__ int2   g_edges[(size_t)NN * CAP]; // (src, weight-as-half2-broadcast)

// ---------------------------------------------------------------------------
// Prep: zero cursors + convert/transpose both weight matrices to fp16.
// ---------------------------------------------------------------------------
__global__ void prep_kernel(const float* __restrict__ W1, const float* __restrict__ W2,
                            __half* __restrict__ W1t, __half* __restrict__ W2t,
                            int* __restrict__ cursor)
{
    int idx = blockIdx.x * blockDim.x + threadIdx.x;
    if (idx < NN) cursor[idx] = 0;
    if (idx < DD * DD) {
        int k = idx >> 7;
        int n = idx & 127;
        W1t[n * DD + k] = __float2half(W1[idx]);
        W2t[n * DD + k] = __float2half(W2[idx]);
    }
}

// ---------------------------------------------------------------------------
// HGEMM via mma.sync m16n8k16 (fp16 in, fp32 acc, fp16 out). R10 verbatim.
// ---------------------------------------------------------------------------
#define GEMM_SMEM ((64 + 128) * 136 * 2)

template <typename InT, bool RELU>
__global__ __launch_bounds__(256) void hgemm_kernel(
    const InT* __restrict__ X, const __half* __restrict__ Wt,
    __half* __restrict__ out)
{
    extern __shared__ __align__(16) __half sh[];
    __half (*Ash)[136] = reinterpret_cast<__half(*)[136]>(sh);            // 64 x 136
    __half (*Bsh)[136] = reinterpret_cast<__half(*)[136]>(sh + 64 * 136); // 128 x 136

    const int tid = threadIdx.x;
    const int lane = tid & 31;
    const int wid = tid >> 5;
    const int block_row = blockIdx.x * 64;

#pragma unroll
    for (int i = 0; i < 16; i++) {
        int idx = tid + i * 256;
        int n = idx >> 5;
        int c4 = (idx & 31) * 4;
        uint2 v = *(const uint2*)(Wt + n * DD + c4);
        *(uint2*)&Bsh[n][c4] = v;
    }

    if constexpr (sizeof(InT) == 4) {
#pragma unroll
        for (int i = 0; i < 8; i++) {
            int idx = tid + i * 256;
            int r = idx >> 5;
            int c4 = (idx & 31) * 4;
            int gr = block_row + r;
            float4 v = make_float4(0.f, 0.f, 0.f, 0.f);
            if (gr < NN) v = *(const float4*)((const float*)X + (size_t)gr * DD + c4);
            if (RELU) {
                v.x = fmaxf(v.x, 0.f); v.y = fmaxf(v.y, 0.f);
                v.z = fmaxf(v.z, 0.f); v.w = fmaxf(v.w, 0.f);
            }
            __half2 h0 = __floats2half2_rn(v.x, v.y);
            __half2 h1 = __floats2half2_rn(v.z, v.w);
            uint2 pk;
            pk.x = *reinterpret_cast<uint*>(&h0);
            pk.y = *reinterpret_cast<uint*>(&h1);
            *(uint2*)&Ash[r][c4] = pk;
        }
    } else {
#pragma unroll
        for (int i = 0; i < 8; i++) {
            int idx = tid + i * 256;
            int r = idx >> 5;
            int c4 = (idx & 31) * 4;
            int gr = block_row + r;
            uint2 v = make_uint2(0u, 0u);
            if (gr < NN) v = *(const uint2*)((const __half*)X + (size_t)gr * DD + c4);
            if (RELU) {
                __half2 z = __float2half2_rn(0.f);
                __half2 a = __hmax2(*reinterpret_cast<__half2*>(&v.x), z);
                __half2 b = __hmax2(*reinterpret_cast<__half2*>(&v.y), z);
                v.x = *reinterpret_cast<uint*>(&a);
                v.y = *reinterpret_cast<uint*>(&b);
            }
            *(uint2*)&Ash[r][c4] = v;
        }
    }
    __syncthreads();

    const int warp_m = (wid >> 2) * 32;
    const int warp_n = (wid & 3) * 32;
    const int gr = lane >> 2;
    const int qc = lane & 3;

    float acc[2][4][4];
#pragma unroll
    for (int mt = 0; mt < 2; mt++)
#pragma unroll
        for (int nt = 0; nt < 4; nt++)
#pragma unroll
            for (int j = 0; j < 4; j++) acc[mt][nt][j] = 0.f;

#pragma unroll
    for (int k0 = 0; k0 < DD; k0 += 16) {
        int kc = k0 + 2 * qc;
        uint a[2][4];
#pragma unroll
        for (int mt = 0; mt < 2; mt++) {
            int r0 = warp_m + mt * 16 + gr;
            a[mt][0] = *(const uint*)&Ash[r0][kc];
            a[mt][1] = *(const uint*)&Ash[r0 + 8][kc];
            a[mt][2] = *(const uint*)&Ash[r0][kc + 8];
            a[mt][3] = *(const uint*)&Ash[r0 + 8][kc + 8];
        }
#pragma unroll
        for (int nt = 0; nt < 4; nt++) {
            int n = warp_n + nt * 8 + gr;
            uint b0 = *(const uint*)&Bsh[n][kc];
            uint b1 = *(const uint*)&Bsh[n][kc + 8];
#pragma unroll
            for (int mt = 0; mt < 2; mt++) {
                asm volatile(
                    "mma.sync.aligned.m16n8k16.row.col.f32.f16.f16.f32 "
                    "{%0,%1,%2,%3}, {%4,%5,%6,%7}, {%8,%9}, {%0,%1,%2,%3};"
                    : "+f"(acc[mt][nt][0]), "+f"(acc[mt][nt][1]),
                      "+f"(acc[mt][nt][2]), "+f"(acc[mt][nt][3])
                    : "r"(a[mt][0]), "r"(a[mt][1]), "r"(a[mt][2]), "r"(a[mt][3]),
                      "r"(b0), "r"(b1));
            }
        }
    }

#pragma unroll
    for (int mt = 0; mt < 2; mt++) {
        int r0 = block_row + warp_m + mt * 16 + gr;
#pragma unroll
        for (int nt = 0; nt < 4; nt++) {
            int col = warp_n + nt * 8 + 2 * qc;
            if (r0 < NN) {
                __half2 p = __floats2half2_rn(acc[mt][nt][0], acc[mt][nt][1]);
                *(__half2*)(out + (size_t)r0 * DD + col) = p;
            }
            if (r0 + 8 < NN) {
                __half2 p = __floats2half2_rn(acc[mt][nt][2], acc[mt][nt][3]);
                *(__half2*)(out + (size_t)(r0 + 8) * DD + col) = p;
            }
        }
    }
}

// ---------------------------------------------------------------------------
// Bucket fill: one edge per thread. Weight pre-converted to broadcast half2.
// ---------------------------------------------------------------------------
__global__ void fill_kernel(
    const int* __restrict__ src, const int* __restrict__ dst,
    const float* __restrict__ w, int* __restrict__ cursor,
    int2* __restrict__ edges, int nE)
{
    int e = blockIdx.x * blockDim.x + threadIdx.x;
    if (e >= nE) return;
    int d = __ldg(dst + e);
    int slot = atomicAdd(cursor + d, 1);
    __half2 w2 = __float2half2_rn(__ldg(w + e));
    edges[(size_t)d * CAP + slot] =
        make_int2(__ldg(src + e), (int)*reinterpret_cast<uint*>(&w2));
}

// ---------------------------------------------------------------------------
// Gather-aggregate: warp per node, 16 lanes per edge. Single rounded-16 loop.
// ONE coalesced LDG.128 per wave fetches all 16 edge records (128B block);
// lane l8 of each half-warp holds records {2*l8, 2*l8+1}. Half 0 processes
// even records (shfl from lane u), half 1 odd records (shfl from lane 16+u).
// 8 independent LDG.128 row loads per wave, HFMA2 accumulate, fp32 flush.
// Padding slots are (0,0).
// ---------------------------------------------------------------------------
template <typename OutT>
__global__ __launch_bounds__(256) void gather_kernel(
    const __half* __restrict__ sup,
    const int2* __restrict__ edges,
    const int* __restrict__ cursor, const float* __restrict__ bias,
    OutT* __restrict__ out)
{
    int n = (int)((blockIdx.x * (unsigned)blockDim.x + threadIdx.x) >> 5);
    int lane = threadIdx.x & 31;
    if (n >= NN) return;

    const int half_id = lane >> 4;       // 0: even records, 1: odd records
    const int fl = lane & 15;            // feature slice: halfs [fl*8, fl*8+8)
    const int l8 = lane & 7;             // record-pair owner within wave
    const int src_base = half_id << 4;   // shfl source base: 0 or 16

    const uint4* recbase = (const uint4*)(edges + (size_t)n * CAP);  // 16B aligned
    const int row_off = fl * 8;
    int deg = __ldg(cursor + n);

    float acc[8];
#pragma unroll
    for (int j = 0; j < 8; j++) acc[j] = 0.f;

    for (int k = 0; k < deg; k += 16) {       // 16 edges per wave (padded w=0)
        // One coalesced 128B load: lane l8 holds records 2*l8 and 2*l8+1.
        uint4 q = __ldg(recbase + (k >> 1) + l8);
        // This lane exposes record 2*l8 + half_id.
        int  mySrc = half_id ? (int)q.z : (int)q.x;
        uint myW   = half_id ? q.w       : q.y;

        __half2 w2[8];
        const __half* rp[8];
#pragma unroll
        for (int u = 0; u < 8; u++) {
            // Source lane (src_base+u) has l8=u and our half_id -> record 2u+half_id.
            int  s  = __shfl_sync(0xffffffffu, mySrc, src_base + u);
            uint wv = __shfl_sync(0xffffffffu, myW,  src_base + u);
            w2[u] = *reinterpret_cast<__half2*>(&wv);
            rp[u] = sup + (size_t)s * DD + row_off;
        }
        uint4 v[8];
#pragma unroll
        for (int u = 0; u < 8; u++) v[u] = *(const uint4*)rp[u];

        __half2 hacc[4];
#pragma unroll
        for (int j = 0; j < 4; j++) hacc[j] = __float2half2_rn(0.f);
#pragma unroll
        for (int u = 0; u < 8; u++) {
            hacc[0] = __hfma2(w2[u], *reinterpret_cast<__half2*>(&v[u].x), hacc[0]);
            hacc[1] = __hfma2(w2[u], *reinterpret_cast<__half2*>(&v[u].y), hacc[1]);
            hacc[2] = __hfma2(w2[u], *reinterpret_cast<__half2*>(&v[u].z), hacc[2]);
            hacc[3] = __hfma2(w2[u], *reinterpret_cast<__half2*>(&v[u].w), hacc[3]);
        }
#pragma unroll
        for (int j = 0; j < 4; j++) {
            float2 f = __half22float2(hacc[j]);
            acc[2 * j + 0] += f.x;
            acc[2 * j + 1] += f.y;
        }
    }

#pragma unroll
    for (int j = 0; j < 8; j++)
        acc[j] += __shfl_xor_sync(0xffffffffu, acc[j], 16);

    if (lane < 16) {
        const float* bp = bias + row_off;
#pragma unroll
        for (int j = 0; j < 8; j++) acc[j] += __ldg(bp + j);

        if constexpr (sizeof(OutT) == 4) {
            float* op = (float*)out + (size_t)n * DD + row_off;
            *(float4*)(op) = make_float4(acc[0], acc[1], acc[2], acc[3]);
            *(float4*)(op + 4) = make_float4(acc[4], acc[5], acc[6], acc[7]);
        } else {
            __half2 h0 = __floats2half2_rn(acc[0], acc[1]);
            __half2 h1 = __floats2half2_rn(acc[2], acc[3]);
            __half2 h2 = __floats2half2_rn(acc[4], acc[5]);
            __half2 h3 = __floats2half2_rn(acc[6], acc[7]);
            uint4 pk;
            pk.x = *reinterpret_cast<uint*>(&h0);
            pk.y = *reinterpret_cast<uint*>(&h1);
            pk.z = *reinterpret_cast<uint*>(&h2);
            pk.w = *reinterpret_cast<uint*>(&h3);
            *(uint4*)((__half*)out + (size_t)n * DD + row_off) = pk;
        }
    }
}

// ---------------------------------------------------------------------------
// kernel_launch — plain serial pipeline (R10 structure).
// ---------------------------------------------------------------------------
extern "C" void kernel_launch(void* const* d_in, const int* in_sizes, int n_in,
                              void* d_out, int out_size)
{
    const float* features = (const float*)d_in[0];
    const int*   edge_src = (const int*)d_in[1];
    const int*   edge_dst = (const int*)d_in[2];
    const float* edge_w   = (const float*)d_in[3];
    const float* W1       = (const float*)d_in[4];
    const float* b1       = (const float*)d_in[5];
    const float* W2       = (const float*)d_in[6];
    const float* b2       = (const float*)d_in[7];
    float* out = (float*)d_out;

    const int nE = in_sizes[1];

    __half* sup;  cudaGetSymbolAddress((void**)&sup, g_sup);
    __half* h;    cudaGetSymbolAddress((void**)&h, g_h);
    __half* w1t;  cudaGetSymbolAddress((void**)&w1t, g_w1t);
    __half* w2t;  cudaGetSymbolAddress((void**)&w2t, g_w2t);
    int* cursor;  cudaGetSymbolAddress((void**)&cursor, g_cursor);
    int2* edges;  cudaGetSymbolAddress((void**)&edges, g_edges);

    cudaFuncSetAttribute(hgemm_kernel<float, false>,
                         cudaFuncAttributeMaxDynamicSharedMemorySize, GEMM_SMEM);
    cudaFuncSetAttribute(hgemm_kernel<__half, true>,
                         cudaFuncAttributeMaxDynamicSharedMemorySize, GEMM_SMEM);

    const int gemm_grid = (NN + 63) / 64;
    const int edge_grid = (nE + 255) / 256;
    const int prep_grid = (NN + 255) / 256;
    const int gather_grid = (NN * 32 + 255) / 256;

    prep_kernel<<<prep_grid, 256>>>(W1, W2, w1t, w2t, cursor);
    fill_kernel<<<edge_grid, 256>>>(edge_src, edge_dst, edge_w, cursor, edges, nE);

    hgemm_kernel<float, false><<<gemm_grid, 256, GEMM_SMEM>>>(features, w1t, sup);
    gather_kernel<__half><<<gather_grid, 256>>>(sup, edges, cursor, b1, h);

    hgemm_kernel<__half, true><<<gemm_grid, 256, GEMM_SMEM>>>(h, w2t, sup);
    gather_kernel<float><<<gather_grid, 256>>>(sup, edges, cursor, b2, out);
}